// round 9
// baseline (speedup 1.0000x reference)
#include <cuda_runtime.h>
#include <cuda_fp16.h>
#include <stdint.h>

#define NB 8
#define NH 16
#define NS 1024
#define ND 128

// smem layout (bytes)
#define SM_KH 0
#define SM_KL 32768
#define SM_VH 65536
#define SM_VL 98304
#define SM_SC 131072            // staged scale half-tile: 128 rows x 288B
#define SM_SC0 167936           // staged rsqrt(scale0)*log2e half-tile
#define SC_STRIDE 288
#define SMEM_TOTAL 204800

#define DEVFN static __device__ __forceinline__

// 64MB device scratch: rsqrt(scale[0]) * log2e
__device__ float g_r0[(size_t)NH * NS * NS];

DEVFN uint32_t smem_u32(const void* p){
  uint32_t a;
  asm("{.reg .u64 t; cvta.to.shared.u64 t,%1; cvt.u32.u64 %0,t;}":"=r"(a):"l"(p));
  return a;
}
DEVFN uint32_t swz(int r, int c){
  return (uint32_t)(r*256 + ((((c>>3) ^ (r&7)) & 15) << 4) + (c&7)*2);
}
DEVFN float f16rt(float x){ return __half2float(__float2half_rn(x)); }
DEVFN uint32_t pkh(float lo, float hi){
  uint32_t r; asm("cvt.rn.f16x2.f32 %0,%1,%2;":"=r"(r):"f"(hi),"f"(lo)); return r;
}
DEVFN float ex2(float x){ float y; asm("ex2.approx.ftz.f32 %0,%1;":"=f"(y):"f"(x)); return y; }
DEVFN void ldsm4(uint32_t* r, uint32_t addr){
  asm volatile("ldmatrix.sync.aligned.m8n8.x4.shared.b16 {%0,%1,%2,%3},[%4];"
    : "=r"(r[0]),"=r"(r[1]),"=r"(r[2]),"=r"(r[3]) : "r"(addr));
}
DEVFN void ldsm4t(uint32_t* r, uint32_t addr){
  asm volatile("ldmatrix.sync.aligned.m8n8.x4.trans.shared.b16 {%0,%1,%2,%3},[%4];"
    : "=r"(r[0]),"=r"(r[1]),"=r"(r[2]),"=r"(r[3]) : "r"(addr));
}
DEVFN void mma16816(float* d, const uint32_t* a, const uint32_t* b){
  asm volatile("mma.sync.aligned.m16n8k16.row.col.f32.f16.f16.f32 "
    "{%0,%1,%2,%3},{%4,%5,%6,%7},{%8,%9},{%0,%1,%2,%3};"
    : "+f"(d[0]),"+f"(d[1]),"+f"(d[2]),"+f"(d[3])
    : "r"(a[0]),"r"(a[1]),"r"(a[2]),"r"(a[3]), "r"(b[0]),"r"(b[1]));
}
DEVFN void cvst(char* smb, int offH, int offL, int r, int c, float4 v){
  float h0=f16rt(v.x), h1=f16rt(v.y), h2=f16rt(v.z), h3=f16rt(v.w);
  uint32_t o = swz(r, c);
  *(uint2*)(smb+offH+o) = make_uint2(pkh(h0,h1), pkh(h2,h3));
  *(uint2*)(smb+offL+o) = make_uint2(pkh(v.x-h0,v.y-h1), pkh(v.z-h2,v.w-h3));
}
DEVFN void cpa16(uint32_t dst, const void* src){
  asm volatile("cp.async.ca.shared.global [%0],[%1],16;"::"r"(dst),"l"(src));
}
DEVFN void cpa_commit(){ asm volatile("cp.async.commit_group;":::"memory"); }
DEVFN void cpa_wait0(){ asm volatile("cp.async.wait_group 0;":::"memory"); }

// stage 128 rows x 64 cols (key half hf) of scale + r0 into smem
DEVFN void stage_half(uint32_t sb, const float* sgc, const float* r0c, int hf, int tid){
  int r = tid>>1;
  int c0 = hf*64 + (tid&1)*32;
  const float* ps = sgc + (size_t)r*NS + c0;
  const float* p0 = r0c + (size_t)r*NS + c0;
  uint32_t ds = sb + SM_SC  + (uint32_t)r*SC_STRIDE + (tid&1)*128;
  uint32_t d0 = sb + SM_SC0 + (uint32_t)r*SC_STRIDE + (tid&1)*128;
#pragma unroll
  for (int i=0;i<8;++i){
    cpa16(ds + i*16, ps + i*4);
    cpa16(d0 + i*16, p0 + i*4);
  }
}

__global__ void prep_r0(const float* __restrict__ sg){
  size_t i = (size_t)blockIdx.x*256 + threadIdx.x;   // over NH*NS*NS/4 float4s
  float4 v = ((const float4*)sg)[i];
  v.x = rsqrtf(v.x)*1.44269504f;
  v.y = rsqrtf(v.y)*1.44269504f;
  v.z = rsqrtf(v.z)*1.44269504f;
  v.w = rsqrtf(v.w)*1.44269504f;
  ((float4*)g_r0)[i] = v;
}

__global__ void __launch_bounds__(256,1)
attn_kernel(const float* __restrict__ qg, const float* __restrict__ kg,
            const float* __restrict__ vg, const float* __restrict__ sg,
            float* __restrict__ out)
{
  extern __shared__ char sm[];
  uint32_t sb = smem_u32(sm);
  int tid = threadIdx.x, wid = tid>>5, lane = tid&31;
  int x = blockIdx.x;
  int b = x&7, qt = (x>>3)&7, h = x>>6;
  int q0 = qt*128;

  // ---- stage Q into smem (reuse K buffers), build fp16 hi/lo A-fragments ----
  const float* Q = qg + (((size_t)b*NH + h)*NS + q0)*ND;
#pragma unroll
  for (int it=0; it<16; ++it){
    int j = tid + it*256; int r = j>>5, c = (j&31)*4;
    cvst(sm, SM_KH, SM_KL, r, c, *(const float4*)(Q + (size_t)r*ND + c));
  }
  __syncthreads();

  uint32_t qh[8][4], ql[8][4];
  {
    int rowa = wid*16 + ((lane>>3)&1)*8 + (lane&7);
    int cola = (lane>>4)*8;
#pragma unroll
    for (int kc=0; kc<8; ++kc){
      uint32_t off = swz(rowa, kc*16 + cola);
      ldsm4(qh[kc], sb + SM_KH + off);
      ldsm4(ql[kc], sb + SM_KL + off);
    }
  }

  float o[64];
#pragma unroll
  for (int i=0;i<64;++i) o[i]=0.f;
  float m0=-1e30f, m1=-1e30f, rs0=0.f, rs1=0.f;   // in log2 domain

  int rq = wid*16 + (lane>>2);              // q-tile-local row of c0/c1
  const float* sgc = sg + ((((size_t)b*NH + h)*NS + q0)*NS);
  const float* r0c = g_r0 + (((size_t)h*NS + q0)*NS);
  const float* Kg  = kg + (((size_t)b*NH + h)*NS)*ND;
  const float* Vg  = vg + (((size_t)b*NH + h)*NS)*ND;

  int brow = lane&7, bsub = lane>>3;

  for (int kt=0; kt<8; ++kt){
    __syncthreads();
    stage_half(sb, sgc + kt*128, r0c + kt*128, 0, tid);
    cpa_commit();

    // ---- load K, V tiles (fp32 -> fp16 hi/lo, swizzled smem) ----
    const float* K = Kg + (size_t)kt*128*ND;
    const float* V = Vg + (size_t)kt*128*ND;
#pragma unroll
    for (int it=0; it<16; ++it){
      int j = tid + it*256; int r = j>>5, c = (j&31)*4;
      cvst(sm, SM_KH, SM_KL, r, c, *(const float4*)(K + (size_t)r*ND + c));
      cvst(sm, SM_VH, SM_VL, r, c, *(const float4*)(V + (size_t)r*ND + c));
    }
    __syncthreads();

#pragma unroll
    for (int hf=0; hf<2; ++hf){
      // ---- S = Qhi*Khi + Qlo*Khi + Qhi*Klo for 64-key half ----
      float s[32];
#pragma unroll
      for (int i=0;i<32;++i) s[i]=0.f;
#pragma unroll
      for (int kc=0; kc<8; kc+=2){
#pragma unroll
        for (int j=0; j<8; ++j){
          uint32_t bh[4], bl[4];
          uint32_t off = swz(64*hf + 8*j + brow, kc*16 + bsub*8);
          ldsm4(bh, sb + SM_KH + off);
          ldsm4(bl, sb + SM_KL + off);
          mma16816(&s[4*j], qh[kc],   bh);
          mma16816(&s[4*j], ql[kc],   bh);
          mma16816(&s[4*j], qh[kc],   bl);
          mma16816(&s[4*j], qh[kc+1], bh+2);
          mma16816(&s[4*j], ql[kc+1], bh+2);
          mma16816(&s[4*j], qh[kc+1], bl+2);
        }
      }

      // ---- staged multiplier: s *= scale * rsqrt(scale0) * log2e ----
      cpa_wait0();
      __syncthreads();
      float mx0=-1e30f, mx1=-1e30f;
      {
        const char* pA = sm + SM_SC  + rq*SC_STRIDE + (lane&3)*8;
        const char* pT = sm + SM_SC0 + rq*SC_STRIDE + (lane&3)*8;
#pragma unroll
        for (int j=0; j<8; ++j){
          float2 a0 = *(const float2*)(pA + j*32);
          float2 a1 = *(const float2*)(pA + 8*SC_STRIDE + j*32);
          float2 t0 = *(const float2*)(pT + j*32);
          float2 t1 = *(const float2*)(pT + 8*SC_STRIDE + j*32);
          s[4*j+0] *= a0.x * t0.x;
          s[4*j+1] *= a0.y * t0.y;
          s[4*j+2] *= a1.x * t1.x;
          s[4*j+3] *= a1.y * t1.y;
          mx0 = fmaxf(mx0, fmaxf(s[4*j+0], s[4*j+1]));
          mx1 = fmaxf(mx1, fmaxf(s[4*j+2], s[4*j+3]));
        }
      }
      __syncthreads();                 // staging consumed
      if (hf==0){                      // prefetch half-2 under PV-h1 + QK-h2
        stage_half(sb, sgc + kt*128, r0c + kt*128, 1, tid);
        cpa_commit();
      }

      // ---- online softmax update (log2 domain) ----
      mx0 = fmaxf(mx0, __shfl_xor_sync(0xffffffffu, mx0, 1));
      mx0 = fmaxf(mx0, __shfl_xor_sync(0xffffffffu, mx0, 2));
      mx1 = fmaxf(mx1, __shfl_xor_sync(0xffffffffu, mx1, 1));
      mx1 = fmaxf(mx1, __shfl_xor_sync(0xffffffffu, mx1, 2));
      float nm0 = fmaxf(m0, mx0), nm1 = fmaxf(m1, mx1);
      float al0 = ex2(m0 - nm0), al1 = ex2(m1 - nm1);
      m0 = nm0; m1 = nm1;
      rs0 *= al0; rs1 *= al1;
#pragma unroll
      for (int j=0; j<16; ++j){
        o[4*j+0] *= al0; o[4*j+1] *= al0;
        o[4*j+2] *= al1; o[4*j+3] *= al1;
      }

      // ---- exp2, split P into fp16 hi/lo A-fragments ----
      uint32_t pah[4][4], pal[4][4];
#pragma unroll
      for (int j=0; j<8; ++j){
        float p0 = ex2(s[4*j+0] - m0), p1 = ex2(s[4*j+1] - m0);
        float p2 = ex2(s[4*j+2] - m1), p3 = ex2(s[4*j+3] - m1);
        rs0 += p0 + p1; rs1 += p2 + p3;
        float h0=f16rt(p0), h1=f16rt(p1), h2=f16rt(p2), h3=f16rt(p3);
        int kcl = j>>1, q = 2*(j&1);
        pah[kcl][q+0] = pkh(h0, h1);
        pah[kcl][q+1] = pkh(h2, h3);
        pal[kcl][q+0] = pkh(p0-h0, p1-h1);
        pal[kcl][q+1] = pkh(p2-h2, p3-h3);
      }

      // ---- O += Phi*Vhi + Plo*Vhi + Phi*Vlo over this key half ----
#pragma unroll
      for (int kcl=0; kcl<4; kcl+=2){
        int kcg = hf*4 + kcl;
#pragma unroll
        for (int j2=0; j2<16; ++j2){
          uint32_t vh[4], vl[4];
          uint32_t off = swz(kcg*16 + (lane&7) + (lane>>3)*8, 8*j2);
          ldsm4t(vh, sb + SM_VH + off);
          ldsm4t(vl, sb + SM_VL + off);
          mma16816(&o[4*j2], pah[kcl],   vh);
          mma16816(&o[4*j2], pal[kcl],   vh);
          mma16816(&o[4*j2], pah[kcl],   vl);
          mma16816(&o[4*j2], pah[kcl+1], vh+2);
          mma16816(&o[4*j2], pal[kcl+1], vh+2);
          mma16816(&o[4*j2], pah[kcl+1], vl+2);
        }
      }
    }
  }

  // ---- normalize and store ----
  rs0 += __shfl_xor_sync(0xffffffffu, rs0, 1);
  rs0 += __shfl_xor_sync(0xffffffffu, rs0, 2);
  rs1 += __shfl_xor_sync(0xffffffffu, rs1, 1);
  rs1 += __shfl_xor_sync(0xffffffffu, rs1, 2);
  float inv0 = 1.0f/rs0, inv1 = 1.0f/rs1;

  float* O0 = out + (((size_t)b*NH + h)*NS + q0 + rq)*ND + 2*(lane&3);
#pragma unroll
  for (int j2=0; j2<16; ++j2){
    float2 w0, w1;
    w0.x = o[4*j2+0]*inv0; w0.y = o[4*j2+1]*inv0;
    w1.x = o[4*j2+2]*inv1; w1.y = o[4*j2+3]*inv1;
    *(float2*)(O0 + 8*j2) = w0;
    *(float2*)(O0 + 8*ND + 8*j2) = w1;   // row rq+8
  }
}

extern "C" void kernel_launch(void* const* d_in, const int* in_sizes, int n_in,
                              void* d_out, int out_size)
{
  const float* q = (const float*)d_in[0];
  const float* k = (const float*)d_in[1];
  const float* v = (const float*)d_in[2];
  const float* s = (const float*)d_in[3];
  float* o = (float*)d_out;
  // precompute rsqrt(scale[0]) * log2e
  prep_r0<<<(NH*NS*NS/4)/256, 256>>>(s);
  cudaFuncSetAttribute(attn_kernel, cudaFuncAttributeMaxDynamicSharedMemorySize, SMEM_TOTAL);
  attn_kernel<<<NB*NH*(NS/128), 256, SMEM_TOTAL>>>(q, k, v, s, o);
}

// round 10
// speedup vs baseline: 1.6993x; 1.6993x over previous
#include <cuda_runtime.h>
#include <cuda_fp16.h>
#include <stdint.h>

#define NB 8
#define NH 16
#define NS 1024
#define ND 128

// smem: K hi/lo + V hi fp16 tiles (256B rows, XOR-swizzled)
#define SM_KH 0
#define SM_KL 32768
#define SM_VH 65536
#define SMEM_TOTAL 98304

#define DEVFN static __device__ __forceinline__

DEVFN uint32_t smem_u32(const void* p){
  uint32_t a;
  asm("{.reg .u64 t; cvta.to.shared.u64 t,%1; cvt.u32.u64 %0,t;}":"=r"(a):"l"(p));
  return a;
}
DEVFN uint32_t swz(int r, int c){
  return (uint32_t)(r*256 + ((((c>>3) ^ (r&7)) & 15) << 4) + (c&7)*2);
}
DEVFN float f16rt(float x){ return __half2float(__float2half_rn(x)); }
DEVFN uint32_t pkh(float lo, float hi){
  uint32_t r; asm("cvt.rn.f16x2.f32 %0,%1,%2;":"=r"(r):"f"(hi),"f"(lo)); return r;
}
DEVFN void pref(const void* p){ asm volatile("prefetch.global.L2 [%0];"::"l"(p)); }
DEVFN void ldsm4(uint32_t* r, uint32_t addr){
  asm volatile("ldmatrix.sync.aligned.m8n8.x4.shared.b16 {%0,%1,%2,%3},[%4];"
    : "=r"(r[0]),"=r"(r[1]),"=r"(r[2]),"=r"(r[3]) : "r"(addr));
}
DEVFN void ldsm4t(uint32_t* r, uint32_t addr){
  asm volatile("ldmatrix.sync.aligned.m8n8.x4.trans.shared.b16 {%0,%1,%2,%3},[%4];"
    : "=r"(r[0]),"=r"(r[1]),"=r"(r[2]),"=r"(r[3]) : "r"(addr));
}
DEVFN void mma16816(float* d, const uint32_t* a, const uint32_t* b){
  asm volatile("mma.sync.aligned.m16n8k16.row.col.f32.f16.f16.f32 "
    "{%0,%1,%2,%3},{%4,%5,%6,%7},{%8,%9},{%0,%1,%2,%3};"
    : "+f"(d[0]),"+f"(d[1]),"+f"(d[2]),"+f"(d[3])
    : "r"(a[0]),"r"(a[1]),"r"(a[2]),"r"(a[3]), "r"(b[0]),"r"(b[1]));
}
// store float4 chunk of a row as fp16 hi + fp16 lo tiles
DEVFN void cvst(char* smb, int offH, int offL, int r, int c, float4 v){
  float h0=f16rt(v.x), h1=f16rt(v.y), h2=f16rt(v.z), h3=f16rt(v.w);
  uint32_t o = swz(r, c);
  *(uint2*)(smb+offH+o) = make_uint2(pkh(h0,h1), pkh(h2,h3));
  *(uint2*)(smb+offL+o) = make_uint2(pkh(v.x-h0,v.y-h1), pkh(v.z-h2,v.w-h3));
}
// hi-only store (for V)
DEVFN void cvstH(char* smb, int offH, int r, int c, float4 v){
  uint32_t o = swz(r, c);
  *(uint2*)(smb+offH+o) = make_uint2(pkh(f16rt(v.x),f16rt(v.y)), pkh(f16rt(v.z),f16rt(v.w)));
}

__global__ void __launch_bounds__(256,1)
attn_kernel(const float* __restrict__ qg, const float* __restrict__ kg,
            const float* __restrict__ vg, const float* __restrict__ sg,
            float* __restrict__ out)
{
  extern __shared__ char sm[];
  uint32_t sb = smem_u32(sm);
  int tid = threadIdx.x, wid = tid>>5, lane = tid&31;
  int x = blockIdx.x;
  int b = x&7, qt = (x>>3)&7, h = x>>6;
  int q0 = qt*128;

  // ---- stage Q into smem (reuse K buffers), build fp16 hi/lo A-fragments ----
  const float* Q = qg + (((size_t)b*NH + h)*NS + q0)*ND;
#pragma unroll
  for (int it=0; it<16; ++it){
    int j = tid + it*256; int r = j>>5, c = (j&31)*4;
    cvst(sm, SM_KH, SM_KL, r, c, *(const float4*)(Q + (size_t)r*ND + c));
  }
  __syncthreads();

  uint32_t qh[8][4], ql[8][4];
  {
    int rowa = wid*16 + ((lane>>3)&1)*8 + (lane&7);
    int cola = (lane>>4)*8;
#pragma unroll
    for (int kc=0; kc<8; ++kc){
      uint32_t off = swz(rowa, kc*16 + cola);
      ldsm4(qh[kc], sb + SM_KH + off);
      ldsm4(ql[kc], sb + SM_KL + off);
    }
  }

  float o[64];
#pragma unroll
  for (int i=0;i<64;++i) o[i]=0.f;
  float m0=-1e30f, m1=-1e30f, rs0=0.f, rs1=0.f;

  int rq = wid*16 + (lane>>2);              // q-tile-local row of c0/c1
  const float* Sg  = sg + (((size_t)b*NH + h)*NS + q0 + rq)*NS + 2*(lane&3);
  const float* S0g = sg + (((size_t)h)*NS + q0 + rq)*NS + 2*(lane&3);
  const float* Kg  = kg + (((size_t)b*NH + h)*NS)*ND;
  const float* Vg  = vg + (((size_t)b*NH + h)*NS)*ND;

  int brow = lane&7, bsub = lane>>3;

  // prefetch first tile's scale lines into L2
#pragma unroll
  for (int j=0; j<4; ++j){
    pref(Sg  + 32*j); pref(Sg  + 8*NS + 32*j);
    pref(S0g + 32*j); pref(S0g + 8*NS + 32*j);
  }

  for (int kt=0; kt<8; ++kt){
    __syncthreads();
    // ---- load K (hi/lo), V (hi) tiles into swizzled smem ----
    const float* K = Kg + (size_t)kt*128*ND;
    const float* V = Vg + (size_t)kt*128*ND;
#pragma unroll
    for (int it=0; it<16; ++it){
      int j = tid + it*256; int r = j>>5, c = (j&31)*4;
      cvst (sm, SM_KH, SM_KL, r, c, *(const float4*)(K + (size_t)r*ND + c));
      cvstH(sm, SM_VH,        r, c, *(const float4*)(V + (size_t)r*ND + c));
    }
    __syncthreads();

    // ---- S = Qhi*Khi + Qlo*Khi + Qhi*Klo ----
    float s[64];
#pragma unroll
    for (int i=0;i<64;++i) s[i]=0.f;
#pragma unroll
    for (int kc=0; kc<8; kc+=2){
#pragma unroll
      for (int j=0; j<16; ++j){
        uint32_t bh[4], bl[4];
        uint32_t off = swz(8*j + brow, kc*16 + bsub*8);
        ldsm4(bh, sb + SM_KH + off);
        ldsm4(bl, sb + SM_KL + off);
        mma16816(&s[4*j], qh[kc],   bh);
        mma16816(&s[4*j], ql[kc],   bh);
        mma16816(&s[4*j], qh[kc],   bl);
        mma16816(&s[4*j], qh[kc+1], bh+2);
        mma16816(&s[4*j], ql[kc+1], bh+2);
        mma16816(&s[4*j], qh[kc+1], bl+2);
      }
    }

    // ---- elementwise scale * rsqrt(scale0), online max ----
    const float* sA0 = Sg  + kt*128;
    const float* sB0 = S0g + kt*128;
    float mx0=-1e30f, mx1=-1e30f;
#pragma unroll
    for (int j=0; j<16; ++j){
      float2 a0 = *(const float2*)(sA0 + 8*j);
      float2 b0 = *(const float2*)(sB0 + 8*j);
      float2 a1 = *(const float2*)(sA0 + 8*NS + 8*j);
      float2 b1 = *(const float2*)(sB0 + 8*NS + 8*j);
      s[4*j+0] *= a0.x * rsqrtf(b0.x);
      s[4*j+1] *= a0.y * rsqrtf(b0.y);
      s[4*j+2] *= a1.x * rsqrtf(b1.x);
      s[4*j+3] *= a1.y * rsqrtf(b1.y);
      mx0 = fmaxf(mx0, fmaxf(s[4*j+0], s[4*j+1]));
      mx1 = fmaxf(mx1, fmaxf(s[4*j+2], s[4*j+3]));
    }
    // prefetch next tile's scale lines (consumed ~one full tile later)
    if (kt < 7){
      const float* nA = sA0 + 128;
      const float* nB = sB0 + 128;
#pragma unroll
      for (int j=0; j<4; ++j){
        pref(nA + 32*j); pref(nA + 8*NS + 32*j);
        pref(nB + 32*j); pref(nB + 8*NS + 32*j);
      }
    }

    mx0 = fmaxf(mx0, __shfl_xor_sync(0xffffffffu, mx0, 1));
    mx0 = fmaxf(mx0, __shfl_xor_sync(0xffffffffu, mx0, 2));
    mx1 = fmaxf(mx1, __shfl_xor_sync(0xffffffffu, mx1, 1));
    mx1 = fmaxf(mx1, __shfl_xor_sync(0xffffffffu, mx1, 2));
    float nm0 = fmaxf(m0, mx0), nm1 = fmaxf(m1, mx1);
    float al0 = __expf(m0 - nm0), al1 = __expf(m1 - nm1);
    m0 = nm0; m1 = nm1;
    rs0 *= al0; rs1 *= al1;
#pragma unroll
    for (int j=0; j<16; ++j){
      o[4*j+0] *= al0; o[4*j+1] *= al0;
      o[4*j+2] *= al1; o[4*j+3] *= al1;
    }

    // ---- exp, pack P (fp16 single product for PV) ----
    uint32_t pah[8][4];
#pragma unroll
    for (int j=0; j<16; ++j){
      float p0 = __expf(s[4*j+0] - m0), p1 = __expf(s[4*j+1] - m0);
      float p2 = __expf(s[4*j+2] - m1), p3 = __expf(s[4*j+3] - m1);
      rs0 += p0 + p1; rs1 += p2 + p3;
      int kc = j>>1, q = 2*(j&1);
      pah[kc][q+0] = pkh(f16rt(p0), f16rt(p1));
      pah[kc][q+1] = pkh(f16rt(p2), f16rt(p3));
    }

    // prefetch next K/V tile lines during PV phase
    if (kt < 7){
      const float* Kn = K + 128*ND;
      const float* Vn = V + 128*ND;
#pragma unroll
      for (int it=0; it<16; ++it){
        int j = tid + it*256; int r = j>>5, c = (j&31)*4;
        pref(Kn + (size_t)r*ND + c);
        pref(Vn + (size_t)r*ND + c);
      }
    }

    // ---- O += P * Vhi ----
#pragma unroll
    for (int kc=0; kc<8; kc+=2){
#pragma unroll
      for (int j2=0; j2<16; ++j2){
        uint32_t vh[4];
        uint32_t off = swz(kc*16 + (lane&7) + (lane>>3)*8, 8*j2);
        ldsm4t(vh, sb + SM_VH + off);
        mma16816(&o[4*j2], pah[kc],   vh);
        mma16816(&o[4*j2], pah[kc+1], vh+2);
      }
    }
  }

  // ---- normalize and store ----
  rs0 += __shfl_xor_sync(0xffffffffu, rs0, 1);
  rs0 += __shfl_xor_sync(0xffffffffu, rs0, 2);
  rs1 += __shfl_xor_sync(0xffffffffu, rs1, 1);
  rs1 += __shfl_xor_sync(0xffffffffu, rs1, 2);
  float inv0 = 1.0f/rs0, inv1 = 1.0f/rs1;

  float* O0 = out + (((size_t)b*NH + h)*NS + q0 + rq)*ND + 2*(lane&3);
#pragma unroll
  for (int j2=0; j2<16; ++j2){
    float2 w0, w1;
    w0.x = o[4*j2+0]*inv0; w0.y = o[4*j2+1]*inv0;
    w1.x = o[4*j2+2]*inv1; w1.y = o[4*j2+3]*inv1;
    *(float2*)(O0 + 8*j2) = w0;
    *(float2*)(O0 + 8*ND + 8*j2) = w1;   // row rq+8
  }
}

extern "C" void kernel_launch(void* const* d_in, const int* in_sizes, int n_in,
                              void* d_out, int out_size)
{
  const float* q = (const float*)d_in[0];
  const float* k = (const float*)d_in[1];
  const float* v = (const float*)d_in[2];
  const float* s = (const float*)d_in[3];
  float* o = (float*)d_out;
  cudaFuncSetAttribute(attn_kernel, cudaFuncAttributeMaxDynamicSharedMemorySize, SMEM_TOTAL);
  attn_kernel<<<NB*NH*(NS/128), 256, SMEM_TOTAL>>>(q, k, v, s, o);
}

// round 11
// speedup vs baseline: 1.9416x; 1.1426x over previous
#include <cuda_runtime.h>
#include <cuda_fp16.h>
#include <stdint.h>

#define NB 8
#define NH 16
#define NS 1024
#define ND 128

// smem: Q hi/lo persistent + K hi/lo + V hi fp16 tiles (256B rows, XOR-swizzled)
#define SM_QH 0
#define SM_QL 32768
#define SM_KH 65536
#define SM_KL 98304
#define SM_VH 131072
#define SMEM_TOTAL 163840

#define DEVFN static __device__ __forceinline__

DEVFN uint32_t smem_u32(const void* p){
  uint32_t a;
  asm("{.reg .u64 t; cvta.to.shared.u64 t,%1; cvt.u32.u64 %0,t;}":"=r"(a):"l"(p));
  return a;
}
DEVFN uint32_t swz(int r, int c){
  return (uint32_t)(r*256 + ((((c>>3) ^ (r&7)) & 15) << 4) + (c&7)*2);
}
DEVFN float f16rt(float x){ return __half2float(__float2half_rn(x)); }
DEVFN uint32_t pkh(float lo, float hi){
  uint32_t r; asm("cvt.rn.f16x2.f32 %0,%1,%2;":"=r"(r):"f"(hi),"f"(lo)); return r;
}
DEVFN void pref(const void* p){ asm volatile("prefetch.global.L2 [%0];"::"l"(p)); }
DEVFN void ldsm4(uint32_t* r, uint32_t addr){
  asm volatile("ldmatrix.sync.aligned.m8n8.x4.shared.b16 {%0,%1,%2,%3},[%4];"
    : "=r"(r[0]),"=r"(r[1]),"=r"(r[2]),"=r"(r[3]) : "r"(addr));
}
DEVFN void ldsm4t(uint32_t* r, uint32_t addr){
  asm volatile("ldmatrix.sync.aligned.m8n8.x4.trans.shared.b16 {%0,%1,%2,%3},[%4];"
    : "=r"(r[0]),"=r"(r[1]),"=r"(r[2]),"=r"(r[3]) : "r"(addr));
}
DEVFN void mma16816(float* d, const uint32_t* a, const uint32_t* b){
  asm volatile("mma.sync.aligned.m16n8k16.row.col.f32.f16.f16.f32 "
    "{%0,%1,%2,%3},{%4,%5,%6,%7},{%8,%9},{%0,%1,%2,%3};"
    : "+f"(d[0]),"+f"(d[1]),"+f"(d[2]),"+f"(d[3])
    : "r"(a[0]),"r"(a[1]),"r"(a[2]),"r"(a[3]), "r"(b[0]),"r"(b[1]));
}
DEVFN void cvst(char* smb, int offH, int offL, int r, int c, float4 v){
  float h0=f16rt(v.x), h1=f16rt(v.y), h2=f16rt(v.z), h3=f16rt(v.w);
  uint32_t o = swz(r, c);
  *(uint2*)(smb+offH+o) = make_uint2(pkh(h0,h1), pkh(h2,h3));
  *(uint2*)(smb+offL+o) = make_uint2(pkh(v.x-h0,v.y-h1), pkh(v.z-h2,v.w-h3));
}
DEVFN void cvstH(char* smb, int offH, int r, int c, float4 v){
  uint32_t o = swz(r, c);
  *(uint2*)(smb+offH+o) = make_uint2(pkh(f16rt(v.x),f16rt(v.y)), pkh(f16rt(v.z),f16rt(v.w)));
}

__global__ void __launch_bounds__(256,1)
attn_kernel(const float* __restrict__ qg, const float* __restrict__ kg,
            const float* __restrict__ vg, const float* __restrict__ sg,
            float* __restrict__ out)
{
  extern __shared__ char sm[];
  uint32_t sb = smem_u32(sm);
  int tid = threadIdx.x, wid = tid>>5, lane = tid&31;
  int x = blockIdx.x;
  int b = x&7, qt = (x>>3)&7, h = x>>6;
  int q0 = qt*128;

  // ---- stage Q into persistent smem hi/lo ----
  const float* Q = qg + (((size_t)b*NH + h)*NS + q0)*ND;
#pragma unroll
  for (int it=0; it<16; ++it){
    int j = tid + it*256; int r = j>>5, c = (j&31)*4;
    cvst(sm, SM_QH, SM_QL, r, c, *(const float4*)(Q + (size_t)r*ND + c));
  }

  float o[64];
#pragma unroll
  for (int i=0;i<64;++i) o[i]=0.f;
  float m0=-1e30f, m1=-1e30f, rs0=0.f, rs1=0.f;

  int rq = wid*16 + (lane>>2);              // q-tile-local row of c0/c1
  const float* Sg  = sg + (((size_t)b*NH + h)*NS + q0 + rq)*NS + 2*(lane&3);
  const float* S0g = sg + (((size_t)h)*NS + q0 + rq)*NS + 2*(lane&3);
  const float* Kg  = kg + (((size_t)b*NH + h)*NS)*ND;
  const float* Vg  = vg + (((size_t)b*NH + h)*NS)*ND;

  int brow = lane&7, bsub = lane>>3;
  int rowa = wid*16 + ((lane>>3)&1)*8 + (lane&7);   // A-frag ldmatrix row
  int cola = (lane>>4)*8;                           // A-frag ldmatrix col

  // prefetch first tile's scale lines into L2
#pragma unroll
  for (int j=0; j<4; ++j){
    pref(Sg  + 32*j); pref(Sg  + 8*NS + 32*j);
    pref(S0g + 32*j); pref(S0g + 8*NS + 32*j);
  }

  for (int kt=0; kt<8; ++kt){
    __syncthreads();
    // ---- load K (hi/lo), V (hi) tiles into swizzled smem ----
    const float* K = Kg + (size_t)kt*128*ND;
    const float* V = Vg + (size_t)kt*128*ND;
#pragma unroll
    for (int it=0; it<16; ++it){
      int j = tid + it*256; int r = j>>5, c = (j&31)*4;
      cvst (sm, SM_KH, SM_KL, r, c, *(const float4*)(K + (size_t)r*ND + c));
      cvstH(sm, SM_VH,        r, c, *(const float4*)(V + (size_t)r*ND + c));
    }
    __syncthreads();

#pragma unroll
    for (int hf=0; hf<2; ++hf){
      // ---- S = Qhi*Khi + Qlo*Khi + Qhi*Klo for this 64-key half ----
      float s[32];
#pragma unroll
      for (int i=0;i<32;++i) s[i]=0.f;
#pragma unroll
      for (int kc=0; kc<8; kc+=2){
        uint32_t qh0[4], ql0[4], qh1[4], ql1[4];
        uint32_t aoff0 = swz(rowa,  kc   *16 + cola);
        uint32_t aoff1 = swz(rowa, (kc+1)*16 + cola);
        ldsm4(qh0, sb + SM_QH + aoff0);
        ldsm4(ql0, sb + SM_QL + aoff0);
        ldsm4(qh1, sb + SM_QH + aoff1);
        ldsm4(ql1, sb + SM_QL + aoff1);
#pragma unroll
        for (int j=0; j<8; ++j){
          uint32_t bh[4], bl[4];
          uint32_t off = swz(64*hf + 8*j + brow, kc*16 + bsub*8);
          ldsm4(bh, sb + SM_KH + off);
          ldsm4(bl, sb + SM_KL + off);
          mma16816(&s[4*j], qh0, bh);
          mma16816(&s[4*j], ql0, bh);
          mma16816(&s[4*j], qh0, bl);
          mma16816(&s[4*j], qh1, bh+2);
          mma16816(&s[4*j], ql1, bh+2);
          mma16816(&s[4*j], qh1, bl+2);
        }
      }

      // ---- elementwise scale * rsqrt(scale0), online max ----
      const float* sA0 = Sg  + kt*128 + hf*64;
      const float* sB0 = S0g + kt*128 + hf*64;
      float mx0=-1e30f, mx1=-1e30f;
#pragma unroll
      for (int j=0; j<8; ++j){
        float2 a0 = *(const float2*)(sA0 + 8*j);
        float2 b0 = *(const float2*)(sB0 + 8*j);
        float2 a1 = *(const float2*)(sA0 + 8*NS + 8*j);
        float2 b1 = *(const float2*)(sB0 + 8*NS + 8*j);
        s[4*j+0] *= a0.x * rsqrtf(b0.x);
        s[4*j+1] *= a0.y * rsqrtf(b0.y);
        s[4*j+2] *= a1.x * rsqrtf(b1.x);
        s[4*j+3] *= a1.y * rsqrtf(b1.y);
        mx0 = fmaxf(mx0, fmaxf(s[4*j+0], s[4*j+1]));
        mx1 = fmaxf(mx1, fmaxf(s[4*j+2], s[4*j+3]));
      }
      // prefetch next tile's scale lines once per tile
      if (hf==0 && kt<7){
        const float* nA = Sg  + kt*128 + 128;
        const float* nB = S0g + kt*128 + 128;
#pragma unroll
        for (int j=0; j<4; ++j){
          pref(nA + 32*j); pref(nA + 8*NS + 32*j);
          pref(nB + 32*j); pref(nB + 8*NS + 32*j);
        }
      }

      // ---- online softmax update ----
      mx0 = fmaxf(mx0, __shfl_xor_sync(0xffffffffu, mx0, 1));
      mx0 = fmaxf(mx0, __shfl_xor_sync(0xffffffffu, mx0, 2));
      mx1 = fmaxf(mx1, __shfl_xor_sync(0xffffffffu, mx1, 1));
      mx1 = fmaxf(mx1, __shfl_xor_sync(0xffffffffu, mx1, 2));
      float nm0 = fmaxf(m0, mx0), nm1 = fmaxf(m1, mx1);
      float al0 = __expf(m0 - nm0), al1 = __expf(m1 - nm1);
      m0 = nm0; m1 = nm1;
      rs0 *= al0; rs1 *= al1;
#pragma unroll
      for (int j=0; j<16; ++j){
        o[4*j+0] *= al0; o[4*j+1] *= al0;
        o[4*j+2] *= al1; o[4*j+3] *= al1;
      }

      // ---- exp, pack P (fp16 single product for PV) ----
      uint32_t pah[4][4];
#pragma unroll
      for (int j=0; j<8; ++j){
        float p0 = __expf(s[4*j+0] - m0), p1 = __expf(s[4*j+1] - m0);
        float p2 = __expf(s[4*j+2] - m1), p3 = __expf(s[4*j+3] - m1);
        rs0 += p0 + p1; rs1 += p2 + p3;
        int kcl = j>>1, q = 2*(j&1);
        pah[kcl][q+0] = pkh(f16rt(p0), f16rt(p1));
        pah[kcl][q+1] = pkh(f16rt(p2), f16rt(p3));
      }

      // prefetch next K/V tile lines once per tile, during PV phase
      if (hf==1 && kt<7){
        const float* Kn = K + 128*ND;
        const float* Vn = V + 128*ND;
#pragma unroll
        for (int it=0; it<16; ++it){
          int j = tid + it*256; int r = j>>5, c = (j&31)*4;
          pref(Kn + (size_t)r*ND + c);
          pref(Vn + (size_t)r*ND + c);
        }
      }

      // ---- O += P * Vhi over this key half ----
#pragma unroll
      for (int kcl=0; kcl<4; kcl+=2){
        int kcg = hf*4 + kcl;
#pragma unroll
        for (int j2=0; j2<16; ++j2){
          uint32_t vh[4];
          uint32_t off = swz(kcg*16 + (lane&7) + (lane>>3)*8, 8*j2);
          ldsm4t(vh, sb + SM_VH + off);
          mma16816(&o[4*j2], pah[kcl],   vh);
          mma16816(&o[4*j2], pah[kcl+1], vh+2);
        }
      }
    }
  }

  // ---- normalize and store ----
  rs0 += __shfl_xor_sync(0xffffffffu, rs0, 1);
  rs0 += __shfl_xor_sync(0xffffffffu, rs0, 2);
  rs1 += __shfl_xor_sync(0xffffffffu, rs1, 1);
  rs1 += __shfl_xor_sync(0xffffffffu, rs1, 2);
  float inv0 = 1.0f/rs0, inv1 = 1.0f/rs1;

  float* O0 = out + (((size_t)b*NH + h)*NS + q0 + rq)*ND + 2*(lane&3);
#pragma unroll
  for (int j2=0; j2<16; ++j2){
    float2 w0, w1;
    w0.x = o[4*j2+0]*inv0; w0.y = o[4*j2+1]*inv0;
    w1.x = o[4*j2+2]*inv1; w1.y = o[4*j2+3]*inv1;
    *(float2*)(O0 + 8*j2) = w0;
    *(float2*)(O0 + 8*ND + 8*j2) = w1;   // row rq+8
  }
}

extern "C" void kernel_launch(void* const* d_in, const int* in_sizes, int n_in,
                              void* d_out, int out_size)
{
  const float* q = (const float*)d_in[0];
  const float* k = (const float*)d_in[1];
  const float* v = (const float*)d_in[2];
  const float* s = (const float*)d_in[3];
  float* o = (float*)d_out;
  cudaFuncSetAttribute(attn_kernel, cudaFuncAttributeMaxDynamicSharedMemorySize, SMEM_TOTAL);
  attn_kernel<<<NB*NH*(NS/128), 256, SMEM_TOTAL>>>(q, k, v, s, o);
}